// round 5
// baseline (speedup 1.0000x reference)
#include <cuda_runtime.h>

#define NN 50000
#define KD 128      // input dim of both layers (HID == IN_C == 128)
#define H1 128
#define H2 64
#define NE 800000
#define BM 64       // rows per GEMM block

// ---------------- scratch (device globals; float4 => 16B alignment) --------
__device__ float g_deg[NN];
__device__ float g_dinv[NN];
__device__ float4 g_hs1[(size_t)NN * H1 / 4];   // (x@W1)*dinv[row]
__device__ float4 g_acc1[(size_t)NN * H1 / 4];  // scatter accumulator layer 1
__device__ float4 g_x2[(size_t)NN * H1 / 4];    // relu output -> layer2 input
__device__ float4 g_hs2[(size_t)NN * H2 / 4];
__device__ float4 g_acc2[(size_t)NN * H2 / 4];

typedef unsigned long long ull;

#define FMA2(c, a, b) \
    asm("fma.rn.f32x2 %0, %1, %2, %0;" : "+l"(c) : "l"(a), "l"(b))

// ---------------- degree / normalization ----------------------------------
__global__ void k_init_deg() {
    int i = blockIdx.x * blockDim.x + threadIdx.x;
    if (i < NN) g_deg[i] = 1.0f;   // self loop
}

__global__ void k_count_deg(const int* __restrict__ dst) {
    int e = blockIdx.x * blockDim.x + threadIdx.x;
    if (e < NE) atomicAdd(&g_deg[dst[e]], 1.0f);
}

__global__ void k_dinv() {
    int i = blockIdx.x * blockDim.x + threadIdx.x;
    if (i < NN) g_dinv[i] = rsqrtf(g_deg[i]);
}

// ---------------- fused GEMM + dinv scale + self-loop init ----------------
// C[i][j] = (sum_k A[i][k] * W[k][j]) * dinv[i]   -> hs and acc (self loop)
// 256 threads, BM=64 rows x NC cols.  Packed f32x2 math:
//   smem Ws[k][NC+4]        : W, col-pairs natural from float4 loads
//   smem AsD[k][2*BM+4]     : A transposed + duplicated (a_r, a_r) pairs
// thread (tx,ty) 16x16: rows ty*4..+3, cols tx*TN..; TN=NC/16.
template <int NC>
__device__ __forceinline__ void gemm_body(const float* __restrict__ A,
                                          const float* __restrict__ W,
                                          float4* __restrict__ hs,
                                          float4* __restrict__ acc)
{
    constexpr int WS = NC + 4;        // Ws row stride (floats)
    constexpr int AS = 2 * BM + 4;    // AsD row stride (floats)
    constexpr int TN = NC / 16;       // cols per thread: 8 (NC=128) / 4 (NC=64)
    constexpr int TP = TN / 2;        // col-pairs per thread

    extern __shared__ float smem[];
    float* Ws  = smem;                        // [KD][WS]
    float* AsD = smem + (size_t)KD * WS;      // [KD][AS]

    const int tid  = threadIdx.x;
    const int row0 = blockIdx.x * BM;

    // load W (KD x NC), vectorized; rows 16B-aligned (WS*4 multiple of 16)
    for (int i = tid * 4; i < KD * NC; i += 256 * 4) {
        int r = i / NC, c = i % NC;
        *(float4*)(Ws + (size_t)r * WS + c) = *(const float4*)(W + (size_t)r * NC + c);
    }
    // load A tile (BM x KD) -> transposed + duplicated.
    // lanes cover consecutive rows r => dup STS.64 stores are conflict-free.
    for (int idx = tid; idx < BM * (KD / 4); idx += 256) {
        int r  = idx & (BM - 1);
        int c4 = idx >> 6;            // BM==64
        int gr = row0 + r;
        float4 v = make_float4(0.f, 0.f, 0.f, 0.f);
        if (gr < NN) v = *(const float4*)(A + (size_t)gr * KD + c4 * 4);
        float vv[4] = {v.x, v.y, v.z, v.w};
#pragma unroll
        for (int j = 0; j < 4; j++) {
            float2 dup = make_float2(vv[j], vv[j]);
            *(float2*)(AsD + (size_t)(c4 * 4 + j) * AS + 2 * r) = dup;
        }
    }
    __syncthreads();

    const int tx = tid & 15, ty = tid >> 4;
    const int cb = tx * TN;

    ull accp[4][TP];
#pragma unroll
    for (int i = 0; i < 4; i++)
#pragma unroll
        for (int p = 0; p < TP; p++) accp[i][p] = 0ull;

    const float* wrow = Ws  + cb;
    const float* arow = AsD + ty * 8;

#pragma unroll 4
    for (int k = 0; k < KD; k++) {
        float4 a0 = *(const float4*)(arow + (size_t)k * AS);
        float4 a1 = *(const float4*)(arow + (size_t)k * AS + 4);
        ull ap[4];
        ap[0] = ((const ull*)&a0)[0]; ap[1] = ((const ull*)&a0)[1];
        ap[2] = ((const ull*)&a1)[0]; ap[3] = ((const ull*)&a1)[1];

        ull bp[TP];
        float4 b0 = *(const float4*)(wrow + (size_t)k * WS);
        bp[0] = ((const ull*)&b0)[0]; bp[1] = ((const ull*)&b0)[1];
        if (TP == 4) {
            float4 b1 = *(const float4*)(wrow + (size_t)k * WS + 4);
            bp[2] = ((const ull*)&b1)[0]; bp[3] = ((const ull*)&b1)[1];
        }
#pragma unroll
        for (int i = 0; i < 4; i++)
#pragma unroll
            for (int p = 0; p < TP; p++)
                FMA2(accp[i][p], ap[i], bp[p]);
    }

#pragma unroll
    for (int i = 0; i < 4; i++) {
        int gr = row0 + ty * 4 + i;
        if (gr >= NN) continue;
        float d = g_dinv[gr];
        size_t base4 = ((size_t)gr * NC + cb) >> 2;   // float4 index
#pragma unroll
        for (int p2 = 0; p2 < TP / 2; p2++) {
            float2 lo = *(float2*)&accp[i][2 * p2];
            float2 hi = *(float2*)&accp[i][2 * p2 + 1];
            float4 v  = make_float4(lo.x * d, lo.y * d, hi.x * d, hi.y * d);
            hs[base4 + p2]  = v;
            acc[base4 + p2] = v;   // self-loop contribution
        }
    }
}

__global__ void __launch_bounds__(256) k_gemm1(const float* __restrict__ x,
                                               const float* __restrict__ W1) {
    gemm_body<H1>(x, W1, g_hs1, g_acc1);
}
__global__ void __launch_bounds__(256) k_gemm2(const float* __restrict__ W2) {
    gemm_body<H2>((const float*)g_x2, W2, g_hs2, g_acc2);
}

// ---------------- edge scatter: acc[dst] += hs[src] ------------------------
// 128 channels: one warp per edge, each lane handles one float4 (16B).
__global__ void k_scatter1(const int* __restrict__ src,
                           const int* __restrict__ dst)
{
    int w = (blockIdx.x * blockDim.x + threadIdx.x) >> 5;
    if (w >= NE) return;
    int lane = threadIdx.x & 31;
    int s = src[w];
    int d = dst[w];
    float4 v = g_hs1[(size_t)s * (H1 / 4) + lane];
    atomicAdd(&g_acc1[(size_t)d * (H1 / 4) + lane], v);
}

// 64 channels: 16 threads per edge (2 edges per warp), each a float4.
__global__ void k_scatter2(const int* __restrict__ src,
                           const int* __restrict__ dst)
{
    int t = blockIdx.x * blockDim.x + threadIdx.x;
    int e = t >> 4;
    if (e >= NE) return;
    int l = t & 15;
    int s = src[e];
    int d = dst[e];
    float4 v = g_hs2[(size_t)s * (H2 / 4) + l];
    atomicAdd(&g_acc2[(size_t)d * (H2 / 4) + l], v);
}

// ---------------- epilogues ------------------------------------------------
__global__ void k_finish1(const float* __restrict__ b1) {
    int i = blockIdx.x * blockDim.x + threadIdx.x;   // over NN*H1/4 float4s
    if (i >= NN * (H1 / 4)) return;
    int row = i / (H1 / 4);
    int c   = (i % (H1 / 4)) * 4;
    float d = g_dinv[row];
    float4 v = g_acc1[i];
    float4 b = *(const float4*)(b1 + c);
    v.x = fmaxf(fmaf(v.x, d, b.x), 0.f);
    v.y = fmaxf(fmaf(v.y, d, b.y), 0.f);
    v.z = fmaxf(fmaf(v.z, d, b.z), 0.f);
    v.w = fmaxf(fmaf(v.w, d, b.w), 0.f);
    g_x2[i] = v;
}

__global__ void k_finish2(const float* __restrict__ b2, float* __restrict__ out) {
    int i = blockIdx.x * blockDim.x + threadIdx.x;   // over NN*H2/4 float4s
    if (i >= NN * (H2 / 4)) return;
    int row = i / (H2 / 4);
    int c   = (i % (H2 / 4)) * 4;
    float d = g_dinv[row];
    float4 v = g_acc2[i];
    float4 b = *(const float4*)(b2 + c);
    v.x = fmaf(v.x, d, b.x);
    v.y = fmaf(v.y, d, b.y);
    v.z = fmaf(v.z, d, b.z);
    v.w = fmaf(v.w, d, b.w);
    *(float4*)(out + (size_t)row * H2 + c) = v;
}

// ---------------- launch ----------------------------------------------------
extern "C" void kernel_launch(void* const* d_in, const int* in_sizes, int n_in,
                              void* d_out, int out_size)
{
    const float* x  = (const float*)d_in[0];
    const int*   ei = (const int*)d_in[1];    // int32 (JAX default, x64 disabled)
    const float* W1 = (const float*)d_in[2];
    const float* b1 = (const float*)d_in[3];
    const float* W2 = (const float*)d_in[4];
    const float* b2 = (const float*)d_in[5];
    float* out = (float*)d_out;

    const int* src = ei;        // edge_index[0]
    const int* dst = ei + NE;   // edge_index[1]

    const int SMEM1 = (KD * (H1 + 4) + KD * (2 * BM + 4)) * (int)sizeof(float); // 135 KB
    const int SMEM2 = (KD * (H2 + 4) + KD * (2 * BM + 4)) * (int)sizeof(float); // 102 KB
    cudaFuncSetAttribute(k_gemm1, cudaFuncAttributeMaxDynamicSharedMemorySize, SMEM1);
    cudaFuncSetAttribute(k_gemm2, cudaFuncAttributeMaxDynamicSharedMemorySize, SMEM2);

    k_init_deg<<<(NN + 255) / 256, 256>>>();
    k_count_deg<<<(NE + 255) / 256, 256>>>(dst);
    k_dinv<<<(NN + 255) / 256, 256>>>();

    k_gemm1<<<(NN + BM - 1) / BM, 256, SMEM1>>>(x, W1);
    k_scatter1<<<(int)(((size_t)NE * 32 + 255) / 256), 256>>>(src, dst);
    k_finish1<<<(NN * (H1 / 4) + 255) / 256, 256>>>(b1);

    k_gemm2<<<(NN + BM - 1) / BM, 256, SMEM2>>>(W2);
    k_scatter2<<<(int)(((size_t)NE * 16 + 255) / 256), 256>>>(src, dst);
    k_finish2<<<(NN * (H2 / 4) + 255) / 256, 256>>>(b2, out);
}

// round 7
// speedup vs baseline: 1.2767x; 1.2767x over previous
#include <cuda_runtime.h>

#define NN 50000
#define KD 128      // input dim of both layers (HID == IN_C == 128)
#define H1 128
#define H2 64
#define NE 800000
#define BM 128      // rows per GEMM block
#define KC 32       // K chunk

// ---------------- scratch (device globals; float4 => 16B alignment) --------
__device__ float g_deg[NN];
__device__ float g_dinv[NN];
__device__ float4 g_hs1[(size_t)NN * H1 / 4];   // (x@W1)*dinv[row]
__device__ float4 g_acc1[(size_t)NN * H1 / 4];  // scatter accumulator layer 1
__device__ float4 g_x2[(size_t)NN * H1 / 4];    // relu output -> layer2 input
__device__ float4 g_hs2[(size_t)NN * H2 / 4];
__device__ float4 g_acc2[(size_t)NN * H2 / 4];

typedef unsigned long long ull;

#define FMA2(c, a, b) \
    asm("fma.rn.f32x2 %0, %1, %2, %0;" : "+l"(c) : "l"(a), "l"(b))

__device__ __forceinline__ ull dup2(float a) {
    unsigned int u = __float_as_uint(a);
    ull r;
    asm("mov.b64 %0, {%1, %1};" : "=l"(r) : "r"(u));
    return r;
}

// ---------------- degree / normalization ----------------------------------
__global__ void k_init_deg() {
    int i = blockIdx.x * blockDim.x + threadIdx.x;
    if (i < NN) g_deg[i] = 1.0f;   // self loop
}

__global__ void k_count_deg(const int* __restrict__ dst) {
    int e = blockIdx.x * blockDim.x + threadIdx.x;
    if (e < NE) atomicAdd(&g_deg[dst[e]], 1.0f);
}

__global__ void k_dinv() {
    int i = blockIdx.x * blockDim.x + threadIdx.x;
    if (i < NN) g_dinv[i] = rsqrtf(g_deg[i]);
}

// ---------------- fused GEMM + dinv scale + self-loop init ----------------
// C[i][j] = (sum_k A[i][k] * W[k][j]) * dinv[i]  -> hs and acc (self loop)
// 256 threads (tx16 x ty16). BM=128 rows, BN=NC cols, thread tile 8 x TN.
// K chunked (KC=32). A transposed in smem; (a,a) pairs built in registers.
template <int NC>
__device__ __forceinline__ void gemm_body(const float* __restrict__ A,
                                          const float* __restrict__ W,
                                          float4* __restrict__ hs,
                                          float4* __restrict__ acc)
{
    constexpr int TN = NC / 16;       // 8 (NC=128) / 4 (NC=64)
    constexpr int TP = TN / 2;        // col-pairs per thread
    constexpr int WS = NC + 4;        // Wst row stride (floats)
    constexpr int AS = BM + 4;        // Ast row stride (floats)

    extern __shared__ float smem[];
    float* Wst = smem;                        // [KC][WS]
    float* Ast = smem + (size_t)KC * WS;      // [KC][AS] (transposed A)

    const int tid  = threadIdx.x;
    const int tx   = tid & 15, ty = tid >> 4;
    const int row0 = blockIdx.x * BM;
    const int cb   = tx * TN;

    ull accp[8][TP];
#pragma unroll
    for (int i = 0; i < 8; i++)
#pragma unroll
        for (int p = 0; p < TP; p++) accp[i][p] = 0ull;

    for (int k0 = 0; k0 < KD; k0 += KC) {
        // load W chunk (KC x NC), vectorized
        for (int i = tid; i < KC * (NC / 4); i += 256) {
            int kk = i / (NC / 4), c4 = i % (NC / 4);
            *(float4*)(Wst + (size_t)kk * WS + c4 * 4) =
                *(const float4*)(W + (size_t)(k0 + kk) * NC + c4 * 4);
        }
        // load A chunk (BM rows x KC cols) -> transposed Ast[kk][r]
        for (int i = tid; i < BM * (KC / 4); i += 256) {
            int r  = i & (BM - 1);
            int c4 = i >> 7;              // BM==128
            int gr = row0 + r;
            float4 v = make_float4(0.f, 0.f, 0.f, 0.f);
            if (gr < NN) v = *(const float4*)(A + (size_t)gr * KD + k0 + c4 * 4);
            Ast[(size_t)(c4 * 4 + 0) * AS + r] = v.x;
            Ast[(size_t)(c4 * 4 + 1) * AS + r] = v.y;
            Ast[(size_t)(c4 * 4 + 2) * AS + r] = v.z;
            Ast[(size_t)(c4 * 4 + 3) * AS + r] = v.w;
        }
        __syncthreads();

        const float* arow = Ast + ty * 8;
        const float* wrow = Wst + cb;
#pragma unroll 4
        for (int kk = 0; kk < KC; kk++) {
            float4 a0 = *(const float4*)(arow + (size_t)kk * AS);
            float4 a1 = *(const float4*)(arow + (size_t)kk * AS + 4);
            ull ap[8];
            ap[0] = dup2(a0.x); ap[1] = dup2(a0.y);
            ap[2] = dup2(a0.z); ap[3] = dup2(a0.w);
            ap[4] = dup2(a1.x); ap[5] = dup2(a1.y);
            ap[6] = dup2(a1.z); ap[7] = dup2(a1.w);

            ull bp[TP];
            float4 b0 = *(const float4*)(wrow + (size_t)kk * WS);
            bp[0] = ((const ull*)&b0)[0]; bp[1] = ((const ull*)&b0)[1];
            if (TP == 4) {
                float4 b1 = *(const float4*)(wrow + (size_t)kk * WS + 4);
                bp[2] = ((const ull*)&b1)[0]; bp[3] = ((const ull*)&b1)[1];
            }
#pragma unroll
            for (int i = 0; i < 8; i++)
#pragma unroll
                for (int p = 0; p < TP; p++)
                    FMA2(accp[i][p], ap[i], bp[p]);
        }
        __syncthreads();
    }

#pragma unroll
    for (int i = 0; i < 8; i++) {
        int gr = row0 + ty * 8 + i;
        if (gr >= NN) continue;
        float d = g_dinv[gr];
        size_t base4 = ((size_t)gr * NC + cb) >> 2;   // float4 index
#pragma unroll
        for (int p2 = 0; p2 < TP / 2; p2++) {
            float2 lo = *(float2*)&accp[i][2 * p2];
            float2 hi = *(float2*)&accp[i][2 * p2 + 1];
            float4 v  = make_float4(lo.x * d, lo.y * d, hi.x * d, hi.y * d);
            hs[base4 + p2]  = v;
            acc[base4 + p2] = v;   // self-loop contribution
        }
    }
}

__global__ void __launch_bounds__(256, 2) k_gemm1(const float* __restrict__ x,
                                                  const float* __restrict__ W1) {
    gemm_body<H1>(x, W1, g_hs1, g_acc1);
}
__global__ void __launch_bounds__(256, 2) k_gemm2(const float* __restrict__ W2) {
    gemm_body<H2>((const float*)g_x2, W2, g_hs2, g_acc2);
}

// ---------------- edge scatter: acc[dst] += hs[src] ------------------------
// 128 channels: one warp per edge, each lane handles one float4 (16B).
__global__ void k_scatter1(const int* __restrict__ src,
                           const int* __restrict__ dst)
{
    int w = (blockIdx.x * blockDim.x + threadIdx.x) >> 5;
    if (w >= NE) return;
    int lane = threadIdx.x & 31;
    int s = src[w];
    int d = dst[w];
    float4 v = g_hs1[(size_t)s * (H1 / 4) + lane];
    atomicAdd(&g_acc1[(size_t)d * (H1 / 4) + lane], v);
}

// 64 channels: 16 threads per edge (2 edges per warp), each a float4.
__global__ void k_scatter2(const int* __restrict__ src,
                           const int* __restrict__ dst)
{
    int t = blockIdx.x * blockDim.x + threadIdx.x;
    int e = t >> 4;
    if (e >= NE) return;
    int l = t & 15;
    int s = src[e];
    int d = dst[e];
    float4 v = g_hs2[(size_t)s * (H2 / 4) + l];
    atomicAdd(&g_acc2[(size_t)d * (H2 / 4) + l], v);
}

// ---------------- epilogues ------------------------------------------------
__global__ void k_finish1(const float* __restrict__ b1) {
    int i = blockIdx.x * blockDim.x + threadIdx.x;   // over NN*H1/4 float4s
    if (i >= NN * (H1 / 4)) return;
    int row = i / (H1 / 4);
    int c   = (i % (H1 / 4)) * 4;
    float d = g_dinv[row];
    float4 v = g_acc1[i];
    float4 b = *(const float4*)(b1 + c);
    v.x = fmaxf(fmaf(v.x, d, b.x), 0.f);
    v.y = fmaxf(fmaf(v.y, d, b.y), 0.f);
    v.z = fmaxf(fmaf(v.z, d, b.z), 0.f);
    v.w = fmaxf(fmaf(v.w, d, b.w), 0.f);
    g_x2[i] = v;
}

__global__ void k_finish2(const float* __restrict__ b2, float* __restrict__ out) {
    int i = blockIdx.x * blockDim.x + threadIdx.x;   // over NN*H2/4 float4s
    if (i >= NN * (H2 / 4)) return;
    int row = i / (H2 / 4);
    int c   = (i % (H2 / 4)) * 4;
    float d = g_dinv[row];
    float4 v = g_acc2[i];
    float4 b = *(const float4*)(b2 + c);
    v.x = fmaf(v.x, d, b.x);
    v.y = fmaf(v.y, d, b.y);
    v.z = fmaf(v.z, d, b.z);
    v.w = fmaf(v.w, d, b.w);
    *(float4*)(out + (size_t)row * H2 + c) = v;
}

// ---------------- launch ----------------------------------------------------
extern "C" void kernel_launch(void* const* d_in, const int* in_sizes, int n_in,
                              void* d_out, int out_size)
{
    const float* x  = (const float*)d_in[0];
    const int*   ei = (const int*)d_in[1];    // int32 (JAX default, x64 disabled)
    const float* W1 = (const float*)d_in[2];
    const float* b1 = (const float*)d_in[3];
    const float* W2 = (const float*)d_in[4];
    const float* b2 = (const float*)d_in[5];
    float* out = (float*)d_out;

    const int* src = ei;        // edge_index[0]
    const int* dst = ei + NE;   // edge_index[1]

    const int SMEM1 = (KC * (H1 + 4) + KC * (BM + 4)) * (int)sizeof(float); // ~34 KB
    const int SMEM2 = (KC * (H2 + 4) + KC * (BM + 4)) * (int)sizeof(float); // ~26 KB

    k_init_deg<<<(NN + 255) / 256, 256>>>();
    k_count_deg<<<(NE + 255) / 256, 256>>>(dst);
    k_dinv<<<(NN + 255) / 256, 256>>>();

    k_gemm1<<<(NN + BM - 1) / BM, 256, SMEM1>>>(x, W1);
    k_scatter1<<<(int)(((size_t)NE * 32 + 255) / 256), 256>>>(src, dst);
    k_finish1<<<(NN * (H1 / 4) + 255) / 256, 256>>>(b1);

    k_gemm2<<<(NN + BM - 1) / BM, 256, SMEM2>>>(W2);
    k_scatter2<<<(int)(((size_t)NE * 16 + 255) / 256), 256>>>(src, dst);
    k_finish2<<<(NN * (H2 / 4) + 255) / 256, 256>>>(b2, out);
}

// round 8
// speedup vs baseline: 1.8316x; 1.4346x over previous
#include <cuda_runtime.h>

#define NN 50000
#define KD 128      // input dim of both layers (HID == IN_C == 128)
#define H1 128
#define H2 64
#define NE 800000
#define BM 128      // rows per GEMM block
#define KC 32       // K chunk
#define NB 196      // scan blocks: ceil(NN/256)

// ---------------- scratch (device globals) ---------------------------------
__device__ float g_dinv[NN];
__device__ float4 g_hs1[(size_t)NN * H1 / 4];   // (x@W1)*dinv[row]
__device__ float4 g_x2[(size_t)NN * H1 / 4];    // relu output -> layer2 input
__device__ float4 g_hs2[(size_t)NN * H2 / 4];
__device__ int g_cnt[NN];
__device__ int g_rs[NN + 1];                    // CSR row starts
__device__ int g_cur[NN];                       // fill cursors
__device__ int g_csr[NE];                       // src ids grouped by dst
__device__ int g_part[256];                     // block partial sums
__device__ int g_partex[256];                   // exclusive-scanned partials

typedef unsigned long long ull;

#define FMA2(c, a, b) \
    asm("fma.rn.f32x2 %0, %1, %2, %0;" : "+l"(c) : "l"(a), "l"(b))

__device__ __forceinline__ ull dup2(float a) {
    unsigned int u = __float_as_uint(a);
    ull r;
    asm("mov.b64 %0, {%1, %1};" : "=l"(r) : "r"(u));
    return r;
}

// ---------------- CSR build -------------------------------------------------
__global__ void k_zero_cnt() {
    int i = blockIdx.x * blockDim.x + threadIdx.x;
    if (i < NN) g_cnt[i] = 0;
}

__global__ void k_hist(const int* __restrict__ dst) {
    int e = blockIdx.x * blockDim.x + threadIdx.x;
    if (e < NE) atomicAdd(&g_cnt[dst[e]], 1);
}

__global__ void k_block_sum() {
    __shared__ int sd[256];
    int t = threadIdx.x;
    int i = blockIdx.x * 256 + t;
    sd[t] = (i < NN) ? g_cnt[i] : 0;
    __syncthreads();
    for (int off = 128; off > 0; off >>= 1) {
        if (t < off) sd[t] += sd[t + off];
        __syncthreads();
    }
    if (t == 0) g_part[blockIdx.x] = sd[0];
}

__global__ void k_scan_partials() {
    __shared__ int sd[256];
    int t = threadIdx.x;
    int v = (t < NB) ? g_part[t] : 0;
    sd[t] = v;
    __syncthreads();
    for (int off = 1; off < 256; off <<= 1) {
        int x = (t >= off) ? sd[t - off] : 0;
        __syncthreads();
        sd[t] += x;
        __syncthreads();
    }
    if (t < NB) g_partex[t] = sd[t] - v;
}

__global__ void k_row_start() {
    __shared__ int sd[256];
    int t = threadIdx.x;
    int i = blockIdx.x * 256 + t;
    int v = (i < NN) ? g_cnt[i] : 0;
    sd[t] = v;
    __syncthreads();
    for (int off = 1; off < 256; off <<= 1) {
        int x = (t >= off) ? sd[t - off] : 0;
        __syncthreads();
        sd[t] += x;
        __syncthreads();
    }
    if (i < NN) {
        int rs = g_partex[blockIdx.x] + sd[t] - v;
        g_rs[i]  = rs;
        g_cur[i] = rs;
        g_dinv[i] = rsqrtf((float)(v + 1));   // deg includes self loop
    }
    if (i == NN) g_rs[NN] = NE;
}

__global__ void k_fill(const int* __restrict__ src, const int* __restrict__ dst) {
    int e = blockIdx.x * blockDim.x + threadIdx.x;
    if (e >= NE) return;
    int pos = atomicAdd(&g_cur[dst[e]], 1);
    g_csr[pos] = src[e];
}

// ---------------- fused GEMM + dinv scale ----------------------------------
// hs[i][j] = (sum_k A[i][k] * W[k][j]) * dinv[i]
template <int NC>
__device__ __forceinline__ void gemm_body(const float* __restrict__ A,
                                          const float* __restrict__ W,
                                          float4* __restrict__ hs)
{
    constexpr int TN = NC / 16;       // 8 (NC=128) / 4 (NC=64)
    constexpr int TP = TN / 2;        // col-pairs per thread
    constexpr int WS = NC + 4;        // Wst row stride (floats)
    constexpr int AS = BM + 4;        // Ast row stride (floats)

    extern __shared__ float smem[];
    float* Wst = smem;                        // [KC][WS]
    float* Ast = smem + (size_t)KC * WS;      // [KC][AS] (transposed A)

    const int tid  = threadIdx.x;
    const int tx   = tid & 15, ty = tid >> 4;
    const int row0 = blockIdx.x * BM;
    const int cb   = tx * TN;

    ull accp[8][TP];
#pragma unroll
    for (int i = 0; i < 8; i++)
#pragma unroll
        for (int p = 0; p < TP; p++) accp[i][p] = 0ull;

    for (int k0 = 0; k0 < KD; k0 += KC) {
        for (int i = tid; i < KC * (NC / 4); i += 256) {
            int kk = i / (NC / 4), c4 = i % (NC / 4);
            *(float4*)(Wst + (size_t)kk * WS + c4 * 4) =
                *(const float4*)(W + (size_t)(k0 + kk) * NC + c4 * 4);
        }
        for (int i = tid; i < BM * (KC / 4); i += 256) {
            int r  = i & (BM - 1);
            int c4 = i >> 7;              // BM==128
            int gr = row0 + r;
            float4 v = make_float4(0.f, 0.f, 0.f, 0.f);
            if (gr < NN) v = *(const float4*)(A + (size_t)gr * KD + k0 + c4 * 4);
            Ast[(size_t)(c4 * 4 + 0) * AS + r] = v.x;
            Ast[(size_t)(c4 * 4 + 1) * AS + r] = v.y;
            Ast[(size_t)(c4 * 4 + 2) * AS + r] = v.z;
            Ast[(size_t)(c4 * 4 + 3) * AS + r] = v.w;
        }
        __syncthreads();

        const float* arow = Ast + ty * 8;
        const float* wrow = Wst + cb;
#pragma unroll 4
        for (int kk = 0; kk < KC; kk++) {
            float4 a0 = *(const float4*)(arow + (size_t)kk * AS);
            float4 a1 = *(const float4*)(arow + (size_t)kk * AS + 4);
            ull ap[8];
            ap[0] = dup2(a0.x); ap[1] = dup2(a0.y);
            ap[2] = dup2(a0.z); ap[3] = dup2(a0.w);
            ap[4] = dup2(a1.x); ap[5] = dup2(a1.y);
            ap[6] = dup2(a1.z); ap[7] = dup2(a1.w);

            ull bp[TP];
            float4 b0 = *(const float4*)(wrow + (size_t)kk * WS);
            bp[0] = ((const ull*)&b0)[0]; bp[1] = ((const ull*)&b0)[1];
            if (TP == 4) {
                float4 b1 = *(const float4*)(wrow + (size_t)kk * WS + 4);
                bp[2] = ((const ull*)&b1)[0]; bp[3] = ((const ull*)&b1)[1];
            }
#pragma unroll
            for (int i = 0; i < 8; i++)
#pragma unroll
                for (int p = 0; p < TP; p++)
                    FMA2(accp[i][p], ap[i], bp[p]);
        }
        __syncthreads();
    }

#pragma unroll
    for (int i = 0; i < 8; i++) {
        int gr = row0 + ty * 8 + i;
        if (gr >= NN) continue;
        float d = g_dinv[gr];
        size_t base4 = ((size_t)gr * NC + cb) >> 2;
#pragma unroll
        for (int p2 = 0; p2 < TP / 2; p2++) {
            float2 lo = *(float2*)&accp[i][2 * p2];
            float2 hi = *(float2*)&accp[i][2 * p2 + 1];
            hs[base4 + p2] = make_float4(lo.x * d, lo.y * d, hi.x * d, hi.y * d);
        }
    }
}

__global__ void __launch_bounds__(256, 2) k_gemm1(const float* __restrict__ x,
                                                  const float* __restrict__ W1) {
    gemm_body<H1>(x, W1, g_hs1);
}
__global__ void __launch_bounds__(256, 2) k_gemm2(const float* __restrict__ W2) {
    gemm_body<H2>((const float*)g_x2, W2, g_hs2);
}

// ---------------- CSR pull aggregation -------------------------------------
// Layer 1: one warp per dst node, lane = one float4 of 128 channels.
// out = relu(dinv[d] * (hs1[d] + sum_{src in csr[d]} hs1[src]) + b1)
__global__ void __launch_bounds__(256) k_agg1(const float* __restrict__ b1) {
    int w = blockIdx.x * 8 + (threadIdx.x >> 5);
    if (w >= NN) return;
    int lane = threadIdx.x & 31;

    float4 a = g_hs1[(size_t)w * 32 + lane];   // self loop
    int beg = g_rs[w], end = g_rs[w + 1];
    for (int i = beg; i < end; i += 32) {
        int n = min(32, end - i);
        int sv = (i + lane < end) ? g_csr[i + lane] : 0;
        for (int j = 0; j < n; j++) {
            int s = __shfl_sync(0xffffffffu, sv, j);
            float4 v = g_hs1[(size_t)s * 32 + lane];
            a.x += v.x; a.y += v.y; a.z += v.z; a.w += v.w;
        }
    }
    float d = g_dinv[w];
    float4 b = *(const float4*)(b1 + lane * 4);
    a.x = fmaxf(fmaf(a.x, d, b.x), 0.f);
    a.y = fmaxf(fmaf(a.y, d, b.y), 0.f);
    a.z = fmaxf(fmaf(a.z, d, b.z), 0.f);
    a.w = fmaxf(fmaf(a.w, d, b.w), 0.f);
    g_x2[(size_t)w * 32 + lane] = a;
}

// Layer 2: 16-lane group per dst node (64 channels), writes d_out directly.
__global__ void __launch_bounds__(256) k_agg2(const float* __restrict__ b2,
                                              float* __restrict__ out) {
    int g = blockIdx.x * 16 + (threadIdx.x >> 4);
    if (g >= NN) return;
    int l = threadIdx.x & 15;

    float4 a = g_hs2[(size_t)g * 16 + l];      // self loop
    int beg = g_rs[g], end = g_rs[g + 1];
    for (int i = beg; i < end; i += 16) {
        int n = min(16, end - i);
        int sv = (i + l < end) ? g_csr[i + l] : 0;
        for (int j = 0; j < n; j++) {
            int s = __shfl_sync(0xffffffffu, sv, j, 16);
            float4 v = g_hs2[(size_t)s * 16 + l];
            a.x += v.x; a.y += v.y; a.z += v.z; a.w += v.w;
        }
    }
    float d = g_dinv[g];
    float4 b = *(const float4*)(b2 + l * 4);
    a.x = fmaf(a.x, d, b.x);
    a.y = fmaf(a.y, d, b.y);
    a.z = fmaf(a.z, d, b.z);
    a.w = fmaf(a.w, d, b.w);
    *(float4*)(out + (size_t)g * H2 + l * 4) = a;
}

// ---------------- launch ----------------------------------------------------
extern "C" void kernel_launch(void* const* d_in, const int* in_sizes, int n_in,
                              void* d_out, int out_size)
{
    const float* x  = (const float*)d_in[0];
    const int*   ei = (const int*)d_in[1];    // int32 (JAX default, x64 disabled)
    const float* W1 = (const float*)d_in[2];
    const float* b1 = (const float*)d_in[3];
    const float* W2 = (const float*)d_in[4];
    const float* b2 = (const float*)d_in[5];
    float* out = (float*)d_out;

    const int* src = ei;        // edge_index[0]
    const int* dst = ei + NE;   // edge_index[1]

    const int SMEM1 = (KC * (H1 + 4) + KC * (BM + 4)) * (int)sizeof(float); // ~34 KB
    const int SMEM2 = (KC * (H2 + 4) + KC * (BM + 4)) * (int)sizeof(float); // ~26 KB

    // CSR build
    k_zero_cnt<<<(NN + 255) / 256, 256>>>();
    k_hist<<<(NE + 255) / 256, 256>>>(dst);
    k_block_sum<<<NB, 256>>>();
    k_scan_partials<<<1, 256>>>();
    k_row_start<<<NB, 256>>>();
    k_fill<<<(NE + 255) / 256, 256>>>(src, dst);

    // layer 1
    k_gemm1<<<(NN + BM - 1) / BM, 256, SMEM1>>>(x, W1);
    k_agg1<<<(NN + 7) / 8, 256>>>(b1);

    // layer 2
    k_gemm2<<<(NN + BM - 1) / BM, 256, SMEM2>>>(W2);
    k_agg2<<<(NN + 15) / 16, 256>>>(b2, out);
}

// round 11
// speedup vs baseline: 2.1629x; 1.1809x over previous
#include <cuda_runtime.h>

#define NN 50000
#define KD 128      // input dim of both layers (HID == IN_C == 128)
#define H1 128
#define H2 64
#define NE 800000
#define BM 128      // rows per GEMM block
#define KC 32       // K chunk
#define NB 196      // ceil(NN/256)

// ---------------- scratch (device globals) ---------------------------------
__device__ float g_dinv[NN];
__device__ float4 g_hs1[(size_t)NN * H1 / 4];   // (x@W1)*dinv[row]
__device__ float4 g_x2[(size_t)NN * H1 / 4];    // relu output -> layer2 input
__device__ float4 g_hs2[(size_t)NN * H2 / 4];
__device__ int g_cnt[NN];
__device__ int g_rs[NN];                        // CSR segment starts (unordered)
__device__ int g_cur[NN];                       // fill cursors
__device__ int g_csr[NE];                       // src ids grouped by dst
__device__ int g_total;                         // segment allocator

typedef unsigned long long ull;

#define FMA2(c, a, b) \
    asm("fma.rn.f32x2 %0, %1, %2, %0;" : "+l"(c) : "l"(a), "l"(b))

__device__ __forceinline__ ull dup2(float a) {
    unsigned int u = __float_as_uint(a);
    ull r;
    asm("mov.b64 %0, {%1, %1};" : "=l"(r) : "r"(u));
    return r;
}

__device__ __forceinline__ void cpa16(float* d, const float* s) {
    unsigned sd_ = (unsigned)__cvta_generic_to_shared(d);
    asm volatile("cp.async.cg.shared.global [%0], [%1], 16;" :: "r"(sd_), "l"(s));
}
__device__ __forceinline__ void cpa16z(float* d) {
    unsigned sd_ = (unsigned)__cvta_generic_to_shared(d);
    // ignore-src form: src-size 0 => 16B zero-fill, no global read
    asm volatile("cp.async.cg.shared.global [%0], [%1], 16, 0;"
                 :: "r"(sd_), "l"((const void*)g_dinv));
}

// ---------------- CSR build -------------------------------------------------
__global__ void k_zero_cnt() {
    int i = blockIdx.x * blockDim.x + threadIdx.x;
    if (i < NN) g_cnt[i] = 0;
    if (i == 0) g_total = 0;
}

__global__ void k_hist(const int* __restrict__ dst) {
    int e = blockIdx.x * blockDim.x + threadIdx.x;
    if (e < NE) atomicAdd(&g_cnt[dst[e]], 1);
}

// per-block scan + single block-level atomic => unordered disjoint segments
__global__ void k_alloc() {
    __shared__ int sd[256];
    __shared__ int base;
    int t = threadIdx.x;
    int i = blockIdx.x * 256 + t;
    int v = (i < NN) ? g_cnt[i] : 0;
    sd[t] = v;
    __syncthreads();
    for (int off = 1; off < 256; off <<= 1) {
        int x = (t >= off) ? sd[t - off] : 0;
        __syncthreads();
        sd[t] += x;
        __syncthreads();
    }
    if (t == 255) base = atomicAdd(&g_total, sd[255]);
    __syncthreads();
    if (i < NN) {
        int rs = base + sd[t] - v;
        g_rs[i]  = rs;
        g_cur[i] = rs;
        g_dinv[i] = rsqrtf((float)(v + 1));   // deg includes self loop
    }
}

__global__ void k_fill(const int* __restrict__ src, const int* __restrict__ dst) {
    int e = blockIdx.x * blockDim.x + threadIdx.x;
    if (e >= NE) return;
    int pos = atomicAdd(&g_cur[dst[e]], 1);
    g_csr[pos] = src[e];
}

// ---------------- fused GEMM + dinv scale (cp.async double-buffered) --------
// hs[i][j] = (sum_k A[i][k] * W[k][j]) * dinv[i]
template <int NC>
__device__ __forceinline__ void gemm_body(const float* __restrict__ A,
                                          const float* __restrict__ W,
                                          float4* __restrict__ hs)
{
    constexpr int TN  = NC / 16;      // 8 (NC=128) / 4 (NC=64)
    constexpr int TP  = TN / 2;       // col-pairs per thread
    constexpr int WS  = NC + 4;       // W row stride (floats); 16B-mult rows
    constexpr int AS  = KC + 4;       // A row stride (floats) = 36 -> 144B rows
    constexpr int NCH = KD / KC;      // 4 chunks

    extern __shared__ float smem[];
    float* Wb0 = smem;                        // [2][KC][WS]
    float* Ab0 = smem + 2 * KC * WS;          // [2][BM][AS] row-major

    const int tid  = threadIdx.x;
    const int tx   = tid & 15, ty = tid >> 4;
    const int row0 = blockIdx.x * BM;
    const int cb   = tx * TN;

    auto issue = [&](int c) {
        float* Wb = Wb0 + (c & 1) * KC * WS;
        float* Ab = Ab0 + (c & 1) * BM * AS;
        int k0 = c * KC;
        for (int i = tid; i < KC * (NC / 4); i += 256) {
            int kk = i / (NC / 4), c4 = i % (NC / 4);
            cpa16(Wb + kk * WS + c4 * 4, W + (size_t)(k0 + kk) * NC + c4 * 4);
        }
        for (int i = tid; i < BM * (KC / 4); i += 256) {
            int r = i >> 3, c4 = i & 7;       // KC/4 == 8
            int gr = row0 + r;
            float* d = Ab + r * AS + c4 * 4;
            if (gr < NN) cpa16(d, A + (size_t)gr * KD + k0 + c4 * 4);
            else         cpa16z(d);
        }
        asm volatile("cp.async.commit_group;");
    };

    ull accp[8][TP];
#pragma unroll
    for (int i = 0; i < 8; i++)
#pragma unroll
        for (int p = 0; p < TP; p++) accp[i][p] = 0ull;

    issue(0);
    for (int c = 0; c < NCH; c++) {
        if (c + 1 < NCH) {
            issue(c + 1);
            asm volatile("cp.async.wait_group 1;");
        } else {
            asm volatile("cp.async.wait_group 0;");
        }
        __syncthreads();

        const float* arow = Ab0 + (c & 1) * BM * AS + (ty * 8) * AS;
        const float* wrow = Wb0 + (c & 1) * KC * WS + cb;
#pragma unroll 8
        for (int kk = 0; kk < KC; kk++) {
            ull ap[8];
#pragma unroll
            for (int i = 0; i < 8; i++) ap[i] = dup2(arow[i * AS + kk]);

            ull bp[4];
            float4 b0 = *(const float4*)(wrow + (size_t)kk * WS);
            bp[0] = ((const ull*)&b0)[0]; bp[1] = ((const ull*)&b0)[1];
            if (TP == 4) {
                float4 b1 = *(const float4*)(wrow + (size_t)kk * WS + 4);
                bp[2] = ((const ull*)&b1)[0]; bp[3] = ((const ull*)&b1)[1];
            }
#pragma unroll
            for (int i = 0; i < 8; i++)
#pragma unroll
                for (int p = 0; p < TP; p++)
                    FMA2(accp[i][p], ap[i], bp[p]);
        }
        __syncthreads();
    }

#pragma unroll
    for (int i = 0; i < 8; i++) {
        int gr = row0 + ty * 8 + i;
        if (gr >= NN) continue;
        float d = g_dinv[gr];
        size_t base4 = ((size_t)gr * NC + cb) >> 2;
#pragma unroll
        for (int p2 = 0; p2 < TP / 2; p2++) {
            float2 lo = *(float2*)&accp[i][2 * p2];
            float2 hi = *(float2*)&accp[i][2 * p2 + 1];
            hs[base4 + p2] = make_float4(lo.x * d, lo.y * d, hi.x * d, hi.y * d);
        }
    }
}

__global__ void __launch_bounds__(256, 2) k_gemm1(const float* __restrict__ x,
                                                  const float* __restrict__ W1) {
    gemm_body<H1>(x, W1, g_hs1);
}
__global__ void __launch_bounds__(256, 2) k_gemm2(const float* __restrict__ W2) {
    gemm_body<H2>((const float*)g_x2, W2, g_hs2);
}

// ---------------- CSR pull aggregation -------------------------------------
// Layer 1: one warp per dst node, lane = one float4 of 128 channels.
__global__ void __launch_bounds__(256) k_agg1(const float* __restrict__ b1) {
    int w = blockIdx.x * 8 + (threadIdx.x >> 5);
    if (w >= NN) return;
    int lane = threadIdx.x & 31;

    float4 a = g_hs1[(size_t)w * 32 + lane];   // self loop
    int i   = g_rs[w];
    int end = i + g_cnt[w];
    for (; i + 4 <= end; i += 4) {
        int s0 = g_csr[i], s1 = g_csr[i + 1], s2 = g_csr[i + 2], s3 = g_csr[i + 3];
        float4 v0 = g_hs1[(size_t)s0 * 32 + lane];
        float4 v1 = g_hs1[(size_t)s1 * 32 + lane];
        float4 v2 = g_hs1[(size_t)s2 * 32 + lane];
        float4 v3 = g_hs1[(size_t)s3 * 32 + lane];
        a.x += v0.x + v1.x + v2.x + v3.x;
        a.y += v0.y + v1.y + v2.y + v3.y;
        a.z += v0.z + v1.z + v2.z + v3.z;
        a.w += v0.w + v1.w + v2.w + v3.w;
    }
    for (; i < end; i++) {
        int s = g_csr[i];
        float4 v = g_hs1[(size_t)s * 32 + lane];
        a.x += v.x; a.y += v.y; a.z += v.z; a.w += v.w;
    }
    float d = g_dinv[w];
    float4 b = *(const float4*)(b1 + lane * 4);
    a.x = fmaxf(fmaf(a.x, d, b.x), 0.f);
    a.y = fmaxf(fmaf(a.y, d, b.y), 0.f);
    a.z = fmaxf(fmaf(a.z, d, b.z), 0.f);
    a.w = fmaxf(fmaf(a.w, d, b.w), 0.f);
    g_x2[(size_t)w * 32 + lane] = a;
}

// Layer 2: 16-lane group per dst node (64 channels), writes d_out directly.
__global__ void __launch_bounds__(256) k_agg2(const float* __restrict__ b2,
                                              float* __restrict__ out) {
    int g = blockIdx.x * 16 + (threadIdx.x >> 4);
    if (g >= NN) return;
    int l = threadIdx.x & 15;

    float4 a = g_hs2[(size_t)g * 16 + l];      // self loop
    int i   = g_rs[g];
    int end = i + g_cnt[g];
    for (; i + 4 <= end; i += 4) {
        int s0 = g_csr[i], s1 = g_csr[i + 1], s2 = g_csr[i + 2], s3 = g_csr[i + 3];
        float4 v0 = g_hs2[(size_t)s0 * 16 + l];
        float4 v1 = g_hs2[(size_t)s1 * 16 + l];
        float4 v2 = g_hs2[(size_t)s2 * 16 + l];
        float4 v3 = g_hs2[(size_t)s3 * 16 + l];
        a.x += v0.x + v1.x + v2.x + v3.x;
        a.y += v0.y + v1.y + v2.y + v3.y;
        a.z += v0.z + v1.z + v2.z + v3.z;
        a.w += v0.w + v1.w + v2.w + v3.w;
    }
    for (; i < end; i++) {
        int s = g_csr[i];
        float4 v = g_hs2[(size_t)s * 16 + l];
        a.x += v.x; a.y += v.y; a.z += v.z; a.w += v.w;
    }
    float d = g_dinv[g];
    float4 b = *(const float4*)(b2 + l * 4);
    a.x = fmaf(a.x, d, b.x);
    a.y = fmaf(a.y, d, b.y);
    a.z = fmaf(a.z, d, b.z);
    a.w = fmaf(a.w, d, b.w);
    *(float4*)(out + (size_t)g * H2 + l * 4) = a;
}

// ---------------- launch ----------------------------------------------------
extern "C" void kernel_launch(void* const* d_in, const int* in_sizes, int n_in,
                              void* d_out, int out_size)
{
    const float* x  = (const float*)d_in[0];
    const int*   ei = (const int*)d_in[1];    // int32 (JAX default, x64 disabled)
    const float* W1 = (const float*)d_in[2];
    const float* b1 = (const float*)d_in[3];
    const float* W2 = (const float*)d_in[4];
    const float* b2 = (const float*)d_in[5];
    float* out = (float*)d_out;

    const int* src = ei;        // edge_index[0]
    const int* dst = ei + NE;   // edge_index[1]

    const int SMEM1 = (2 * KC * (H1 + 4) + 2 * BM * (KC + 4)) * (int)sizeof(float); // ~69 KB
    const int SMEM2 = (2 * KC * (H2 + 4) + 2 * BM * (KC + 4)) * (int)sizeof(float); // ~53 KB
    cudaFuncSetAttribute(k_gemm1, cudaFuncAttributeMaxDynamicSharedMemorySize, SMEM1);
    cudaFuncSetAttribute(k_gemm2, cudaFuncAttributeMaxDynamicSharedMemorySize, SMEM2);

    // CSR build
    k_zero_cnt<<<(NN + 255) / 256, 256>>>();
    k_hist<<<(NE + 255) / 256, 256>>>(dst);
    k_alloc<<<NB, 256>>>();
    k_fill<<<(NE + 255) / 256, 256>>>(src, dst);

    // layer 1
    k_gemm1<<<(NN + BM - 1) / BM, 256, SMEM1>>>(x, W1);
    k_agg1<<<(NN + 7) / 8, 256>>>(b1);

    // layer 2
    k_gemm2<<<(NN + BM - 1) / BM, 256, SMEM2>>>(W2);
    k_agg2<<<(NN + 15) / 16, 256>>>(b2, out);
}

// round 12
// speedup vs baseline: 2.2549x; 1.0425x over previous
#include <cuda_runtime.h>

#define NN 50000
#define KD 128      // input dim of both layers (HID == IN_C == 128)
#define H1 128
#define H2 64
#define NE 800000
#define BM 128      // rows per GEMM block
#define KC 32       // K chunk
#define NB 196      // ceil(NN/256)

// ---------------- scratch (device globals) ---------------------------------
__device__ float g_dinv[NN];
__device__ float4 g_hs1[(size_t)NN * H1 / 4];   // x@W1 (unscaled)
__device__ float4 g_x2[(size_t)NN * H1 / 4];    // relu output -> layer2 input
__device__ float4 g_hs2[(size_t)NN * H2 / 4];   // x2@W2 (unscaled)
__device__ int g_cnt[NN];
__device__ int g_rs[NN];                        // CSR segment starts (unordered)
__device__ int g_cur[NN];                       // fill cursors
__device__ int g_csr[NE];                       // src ids grouped by dst
__device__ int g_total;                         // segment allocator

typedef unsigned long long ull;

#define FMA2(c, a, b) \
    asm("fma.rn.f32x2 %0, %1, %2, %0;" : "+l"(c) : "l"(a), "l"(b))

__device__ __forceinline__ ull dup2(float a) {
    unsigned int u = __float_as_uint(a);
    ull r;
    asm("mov.b64 %0, {%1, %1};" : "=l"(r) : "r"(u));
    return r;
}

__device__ __forceinline__ void cpa16(float* d, const float* s) {
    unsigned sd_ = (unsigned)__cvta_generic_to_shared(d);
    asm volatile("cp.async.cg.shared.global [%0], [%1], 16;" :: "r"(sd_), "l"(s));
}
__device__ __forceinline__ void cpa16z(float* d) {
    unsigned sd_ = (unsigned)__cvta_generic_to_shared(d);
    asm volatile("cp.async.cg.shared.global [%0], [%1], 16, 0;"
                 :: "r"(sd_), "l"((const void*)g_dinv));
}

// ---------------- CSR build -------------------------------------------------
__global__ void k_zero_cnt() {
    int i = blockIdx.x * blockDim.x + threadIdx.x;
    if (i < NN) g_cnt[i] = 0;
    if (i == 0) g_total = 0;
}

// 4 edges per thread via int4
__global__ void k_hist(const int* __restrict__ dst) {
    int t = blockIdx.x * blockDim.x + threadIdx.x;
    if (t >= NE / 4) return;
    int4 d4 = ((const int4*)dst)[t];
    atomicAdd(&g_cnt[d4.x], 1);
    atomicAdd(&g_cnt[d4.y], 1);
    atomicAdd(&g_cnt[d4.z], 1);
    atomicAdd(&g_cnt[d4.w], 1);
}

// per-block scan + single block-level atomic => unordered disjoint segments
__global__ void k_alloc() {
    __shared__ int sd[256];
    __shared__ int base;
    int t = threadIdx.x;
    int i = blockIdx.x * 256 + t;
    int v = (i < NN) ? g_cnt[i] : 0;
    sd[t] = v;
    __syncthreads();
    for (int off = 1; off < 256; off <<= 1) {
        int x = (t >= off) ? sd[t - off] : 0;
        __syncthreads();
        sd[t] += x;
        __syncthreads();
    }
    if (t == 255) base = atomicAdd(&g_total, sd[255]);
    __syncthreads();
    if (i < NN) {
        int rs = base + sd[t] - v;
        g_rs[i]  = rs;
        g_cur[i] = rs;
        g_dinv[i] = rsqrtf((float)(v + 1));   // deg includes self loop
    }
}

__global__ void k_fill(const int* __restrict__ src, const int* __restrict__ dst) {
    int t = blockIdx.x * blockDim.x + threadIdx.x;
    if (t >= NE / 4) return;
    int4 s4 = ((const int4*)src)[t];
    int4 d4 = ((const int4*)dst)[t];
    g_csr[atomicAdd(&g_cur[d4.x], 1)] = s4.x;
    g_csr[atomicAdd(&g_cur[d4.y], 1)] = s4.y;
    g_csr[atomicAdd(&g_cur[d4.z], 1)] = s4.z;
    g_csr[atomicAdd(&g_cur[d4.w], 1)] = s4.w;
}

// ---------------- GEMM (cp.async double-buffered), NO dinv scale ------------
// hs[i][j] = sum_k A[i][k] * W[k][j]
template <int NC>
__device__ __forceinline__ void gemm_body(const float* __restrict__ A,
                                          const float* __restrict__ W,
                                          float4* __restrict__ hs)
{
    constexpr int TN  = NC / 16;
    constexpr int TP  = TN / 2;
    constexpr int WS  = NC + 4;
    constexpr int AS  = KC + 4;
    constexpr int NCH = KD / KC;

    extern __shared__ float smem[];
    float* Wb0 = smem;                        // [2][KC][WS]
    float* Ab0 = smem + 2 * KC * WS;          // [2][BM][AS] row-major

    const int tid  = threadIdx.x;
    const int tx   = tid & 15, ty = tid >> 4;
    const int row0 = blockIdx.x * BM;
    const int cb   = tx * TN;

    auto issue = [&](int c) {
        float* Wb = Wb0 + (c & 1) * KC * WS;
        float* Ab = Ab0 + (c & 1) * BM * AS;
        int k0 = c * KC;
        for (int i = tid; i < KC * (NC / 4); i += 256) {
            int kk = i / (NC / 4), c4 = i % (NC / 4);
            cpa16(Wb + kk * WS + c4 * 4, W + (size_t)(k0 + kk) * NC + c4 * 4);
        }
        for (int i = tid; i < BM * (KC / 4); i += 256) {
            int r = i >> 3, c4 = i & 7;       // KC/4 == 8
            int gr = row0 + r;
            float* d = Ab + r * AS + c4 * 4;
            if (gr < NN) cpa16(d, A + (size_t)gr * KD + k0 + c4 * 4);
            else         cpa16z(d);
        }
        asm volatile("cp.async.commit_group;");
    };

    ull accp[8][TP];
#pragma unroll
    for (int i = 0; i < 8; i++)
#pragma unroll
        for (int p = 0; p < TP; p++) accp[i][p] = 0ull;

    issue(0);
    for (int c = 0; c < NCH; c++) {
        if (c + 1 < NCH) {
            issue(c + 1);
            asm volatile("cp.async.wait_group 1;");
        } else {
            asm volatile("cp.async.wait_group 0;");
        }
        __syncthreads();

        const float* arow = Ab0 + (c & 1) * BM * AS + (ty * 8) * AS;
        const float* wrow = Wb0 + (c & 1) * KC * WS + cb;
#pragma unroll 8
        for (int kk = 0; kk < KC; kk++) {
            ull ap[8];
#pragma unroll
            for (int i = 0; i < 8; i++) ap[i] = dup2(arow[i * AS + kk]);

            ull bp[4];
            float4 b0 = *(const float4*)(wrow + (size_t)kk * WS);
            bp[0] = ((const ull*)&b0)[0]; bp[1] = ((const ull*)&b0)[1];
            if (TP == 4) {
                float4 b1 = *(const float4*)(wrow + (size_t)kk * WS + 4);
                bp[2] = ((const ull*)&b1)[0]; bp[3] = ((const ull*)&b1)[1];
            }
#pragma unroll
            for (int i = 0; i < 8; i++)
#pragma unroll
                for (int p = 0; p < TP; p++)
                    FMA2(accp[i][p], ap[i], bp[p]);
        }
        __syncthreads();
    }

#pragma unroll
    for (int i = 0; i < 8; i++) {
        int gr = row0 + ty * 8 + i;
        if (gr >= NN) continue;
        size_t base4 = ((size_t)gr * NC + cb) >> 2;
#pragma unroll
        for (int p2 = 0; p2 < TP / 2; p2++) {
            float2 lo = *(float2*)&accp[i][2 * p2];
            float2 hi = *(float2*)&accp[i][2 * p2 + 1];
            hs[base4 + p2] = make_float4(lo.x, lo.y, hi.x, hi.y);
        }
    }
}

__global__ void __launch_bounds__(256, 2) k_gemm1(const float* __restrict__ x,
                                                  const float* __restrict__ W1) {
    gemm_body<H1>(x, W1, g_hs1);
}
__global__ void __launch_bounds__(256, 2) k_gemm2(const float* __restrict__ W2) {
    gemm_body<H2>((const float*)g_x2, W2, g_hs2);
}

// ---------------- CSR pull aggregation (dinv applied here) ------------------
// out = relu(dinv[d] * (dinv[d]*hs[d] + sum_s dinv[s]*hs[s]) + b)
__global__ void __launch_bounds__(256) k_agg1(const float* __restrict__ b1) {
    int w = blockIdx.x * 8 + (threadIdx.x >> 5);
    if (w >= NN) return;
    int lane = threadIdx.x & 31;

    float dd = g_dinv[w];
    float4 a = g_hs1[(size_t)w * 32 + lane];   // self loop (scale dd below)
    a.x *= dd; a.y *= dd; a.z *= dd; a.w *= dd;

    int i   = g_rs[w];
    int end = i + g_cnt[w];
    for (; i + 4 <= end; i += 4) {
        int s0 = g_csr[i], s1 = g_csr[i + 1], s2 = g_csr[i + 2], s3 = g_csr[i + 3];
        float d0 = g_dinv[s0], d1 = g_dinv[s1], d2 = g_dinv[s2], d3 = g_dinv[s3];
        float4 v0 = g_hs1[(size_t)s0 * 32 + lane];
        float4 v1 = g_hs1[(size_t)s1 * 32 + lane];
        float4 v2 = g_hs1[(size_t)s2 * 32 + lane];
        float4 v3 = g_hs1[(size_t)s3 * 32 + lane];
        a.x += v0.x * d0 + v1.x * d1 + v2.x * d2 + v3.x * d3;
        a.y += v0.y * d0 + v1.y * d1 + v2.y * d2 + v3.y * d3;
        a.z += v0.z * d0 + v1.z * d1 + v2.z * d2 + v3.z * d3;
        a.w += v0.w * d0 + v1.w * d1 + v2.w * d2 + v3.w * d3;
    }
    for (; i < end; i++) {
        int s = g_csr[i];
        float ds = g_dinv[s];
        float4 v = g_hs1[(size_t)s * 32 + lane];
        a.x += v.x * ds; a.y += v.y * ds; a.z += v.z * ds; a.w += v.w * ds;
    }
    float4 b = *(const float4*)(b1 + lane * 4);
    a.x = fmaxf(fmaf(a.x, dd, b.x), 0.f);
    a.y = fmaxf(fmaf(a.y, dd, b.y), 0.f);
    a.z = fmaxf(fmaf(a.z, dd, b.z), 0.f);
    a.w = fmaxf(fmaf(a.w, dd, b.w), 0.f);
    g_x2[(size_t)w * 32 + lane] = a;
}

__global__ void __launch_bounds__(256) k_agg2(const float* __restrict__ b2,
                                              float* __restrict__ out) {
    int g = blockIdx.x * 16 + (threadIdx.x >> 4);
    if (g >= NN) return;
    int l = threadIdx.x & 15;

    float dd = g_dinv[g];
    float4 a = g_hs2[(size_t)g * 16 + l];      // self loop
    a.x *= dd; a.y *= dd; a.z *= dd; a.w *= dd;

    int i   = g_rs[g];
    int end = i + g_cnt[g];
    for (; i + 4 <= end; i += 4) {
        int s0 = g_csr[i], s1 = g_csr[i + 1], s2 = g_csr[i + 2], s3 = g_csr[i + 3];
        float d0 = g_dinv[s0], d1 = g_dinv[s1], d2 = g_dinv[s2], d3 = g_dinv[s3];
        float4 v0 = g_hs2[(size_t)s0 * 16 + l];
        float4 v1 = g_hs2[(size_t)s1 * 16 + l];
        float4 v2 = g_hs2[(size_t)s2 * 16 + l];
        float4 v3 = g_hs2[(size_t)s3 * 16 + l];
        a.x += v0.x * d0 + v1.x * d1 + v2.x * d2 + v3.x * d3;
        a.y += v0.y * d0 + v1.y * d1 + v2.y * d2 + v3.y * d3;
        a.z += v0.z * d0 + v1.z * d1 + v2.z * d2 + v3.z * d3;
        a.w += v0.w * d0 + v1.w * d1 + v2.w * d2 + v3.w * d3;
    }
    for (; i < end; i++) {
        int s = g_csr[i];
        float ds = g_dinv[s];
        float4 v = g_hs2[(size_t)s * 16 + l];
        a.x += v.x * ds; a.y += v.y * ds; a.z += v.z * ds; a.w += v.w * ds;
    }
    float4 b = *(const float4*)(b2 + l * 4);
    a.x = fmaf(a.x, dd, b.x);
    a.y = fmaf(a.y, dd, b.y);
    a.z = fmaf(a.z, dd, b.z);
    a.w = fmaf(a.w, dd, b.w);
    *(float4*)(out + (size_t)g * H2 + l * 4) = a;
}

// ---------------- launch ----------------------------------------------------
extern "C" void kernel_launch(void* const* d_in, const int* in_sizes, int n_in,
                              void* d_out, int out_size)
{
    const float* x  = (const float*)d_in[0];
    const int*   ei = (const int*)d_in[1];    // int32 (JAX default, x64 disabled)
    const float* W1 = (const float*)d_in[2];
    const float* b1 = (const float*)d_in[3];
    const float* W2 = (const float*)d_in[4];
    const float* b2 = (const float*)d_in[5];
    float* out = (float*)d_out;

    const int* src = ei;        // edge_index[0]
    const int* dst = ei + NE;   // edge_index[1]

    const int SMEM1 = (2 * KC * (H1 + 4) + 2 * BM * (KC + 4)) * (int)sizeof(float);
    const int SMEM2 = (2 * KC * (H2 + 4) + 2 * BM * (KC + 4)) * (int)sizeof(float);
    cudaFuncSetAttribute(k_gemm1, cudaFuncAttributeMaxDynamicSharedMemorySize, SMEM1);
    cudaFuncSetAttribute(k_gemm2, cudaFuncAttributeMaxDynamicSharedMemorySize, SMEM2);

    // one-time side-stream + events (created on the correctness call,
    // outside graph capture; reused identically on every call)
    static cudaStream_t s_csr = nullptr;
    static cudaEvent_t  ev_fork = nullptr, ev_join = nullptr;
    if (s_csr == nullptr) {
        cudaStreamCreateWithFlags(&s_csr, cudaStreamNonBlocking);
        cudaEventCreateWithFlags(&ev_fork, cudaEventDisableTiming);
        cudaEventCreateWithFlags(&ev_join, cudaEventDisableTiming);
    }

    // fork: CSR build runs concurrently with gemm1 (no shared state:
    // gemm no longer reads g_dinv)
    cudaEventRecord(ev_fork, (cudaStream_t)0);
    cudaStreamWaitEvent(s_csr, ev_fork, 0);

    k_zero_cnt<<<(NN + 255) / 256, 256, 0, s_csr>>>();
    k_hist<<<(NE / 4 + 255) / 256, 256, 0, s_csr>>>(dst);
    k_alloc<<<NB, 256, 0, s_csr>>>();
    k_fill<<<(NE / 4 + 255) / 256, 256, 0, s_csr>>>(src, dst);
    cudaEventRecord(ev_join, s_csr);

    k_gemm1<<<(NN + BM - 1) / BM, 256, SMEM1>>>(x, W1);

    // join
    cudaStreamWaitEvent((cudaStream_t)0, ev_join, 0);

    k_agg1<<<(NN + 7) / 8, 256>>>(b1);
    k_gemm2<<<(NN + BM - 1) / BM, 256, SMEM2>>>(W2);
    k_agg2<<<(NN + 15) / 16, 256>>>(b2, out);
}